// round 1
// baseline (speedup 1.0000x reference)
#include <cuda_runtime.h>
#include <math.h>

#define B_      2
#define T_      8192
#define D_      256
#define E_      8
#define TWO_D   512
#define N_TOK   16384
#define CAP     2048
#define NELEM   (N_TOK * TWO_D)   /* 8388608 */
#define NPAIR   (N_TOK * D_)      /* 4194304 */

// ---------------- scratch (device globals; no allocation allowed) ------------
__device__ float  g_x_states[NELEM];
__device__ float  g_x_target[NELEM];
__device__ float  g_x_eff[NELEM];
__device__ float  g_pred[NELEM];
__device__ float  g_scoresT[E_ * N_TOK];
__device__ int    g_idx[E_ * CAP];
__device__ float  g_vals[E_ * CAP];
__device__ float  g_counts[N_TOK];
__device__ double g_resnorm;

// ---------------- init: copy x -> x_states, compute phase targets ------------
__global__ void k_init(const float* __restrict__ x,
                       const float* __restrict__ cosp,
                       const float* __restrict__ sinp) {
    int i = blockIdx.x * blockDim.x + threadIdx.x;
    if (i == 0) g_resnorm = 0.0;
    if (i >= NPAIR) return;
    int n = i >> 8;          // token index
    int d = i & 255;
    int t = n & (T_ - 1);
    const float2* x2 = (const float2*)x;
    float2 cur = x2[i];
    ((float2*)g_x_states)[i] = cur;
    float2 tg;
    if (t == 0) {
        tg = cur;
    } else {
        float2 p = x2[i - 256];          // (n-1, d)
        float c = cosp[d], s = sinp[d];
        tg.x = p.x * c - p.y * s;
        tg.y = p.x * s + p.y * c;
    }
    ((float2*)g_x_target)[i] = tg;
}

// ------------- fused: apply prime delays + gate logits + softmax -------------
// one block per token, 256 threads (one per d)
__global__ void k_delays_gate(const float* __restrict__ dgains,
                              const float* __restrict__ gate_w) {
    __shared__ float s_gw[TWO_D * E_];   // 4096 floats
    __shared__ float s_red[64];          // 8 warps x 8 experts
    int n = blockIdx.x;
    int d = threadIdx.x;

    for (int i = d; i < TWO_D * E_; i += 256) s_gw[i] = gate_w[i];

    int t = n & (T_ - 1);
    const float2* xs2 = (const float2*)g_x_states;
    float2 v = xs2[n * 256 + d];

    const int taus[4] = {1, 2, 3, 5};
#pragma unroll
    for (int q = 0; q < 4; q++) {
        int tau = taus[q];
        if (t >= tau) {
            float2 s = xs2[(n - tau) * 256 + d];
            float gr = dgains[(q * 256 + d) * 2 + 0];
            float gi = dgains[(q * 256 + d) * 2 + 1];
            v.x += s.x * gr - s.y * gi;
            v.y += s.x * gi + s.y * gr;
        }
    }
    ((float2*)g_x_eff)[n * 256 + d] = v;
    __syncthreads();

    float p[E_];
#pragma unroll
    for (int e = 0; e < E_; e++)
        p[e] = v.x * s_gw[(2 * d) * E_ + e] + v.y * s_gw[(2 * d + 1) * E_ + e];

#pragma unroll
    for (int o = 16; o > 0; o >>= 1)
#pragma unroll
        for (int e = 0; e < E_; e++)
            p[e] += __shfl_down_sync(0xffffffffu, p[e], o);

    int warp = d >> 5, lane = d & 31;
    if (lane == 0)
#pragma unroll
        for (int e = 0; e < E_; e++) s_red[warp * E_ + e] = p[e];
    __syncthreads();

    if (d < E_) {
        float logit = 0.f;
#pragma unroll
        for (int w = 0; w < 8; w++) logit += s_red[w * E_ + d];
        float m = logit;
#pragma unroll
        for (int o = 4; o > 0; o >>= 1)
            m = fmaxf(m, __shfl_xor_sync(0x000000ffu, m, o, 8));
        float ex = expf(logit - m);
        float s = ex;
#pragma unroll
        for (int o = 4; o > 0; o >>= 1)
            s += __shfl_xor_sync(0x000000ffu, s, o, 8);
        g_scoresT[d * N_TOK + n] = ex / s;
    }
}

// -------- per-expert top-CAP selection (byte radix select + ordered compact) -
// 8 blocks (one per expert), 1024 threads, 64KB dynamic smem
__global__ void k_topk() {
    extern __shared__ unsigned u[];      // 16384 flipped keys
    __shared__ int      hist[256];
    __shared__ unsigned s_prefix;
    __shared__ int      s_K;
    __shared__ int      s_cgt;
    __shared__ int      base_gt, base_ti;
    __shared__ int      wtot_gt[32], wtot_ti[32];

    int e = blockIdx.x;
    int tid = threadIdx.x;
    const float* sc = g_scoresT + e * N_TOK;

    for (int i = tid; i < N_TOK; i += 1024) {
        unsigned v = __float_as_uint(sc[i]);
        v = (v & 0x80000000u) ? ~v : (v | 0x80000000u);
        u[i] = v;
    }
    if (tid == 0) { s_prefix = 0u; s_K = CAP; s_cgt = 0; base_gt = 0; base_ti = 0; }
    __syncthreads();

    // radix select: find value of CAP-th largest key
    for (int level = 0; level < 4; level++) {
        int shift = 24 - 8 * level;
        unsigned hm = (level == 0) ? 0u : (0xFFFFFFFFu << (shift + 8));
        if (tid < 256) hist[tid] = 0;
        __syncthreads();
        unsigned pref = s_prefix;
        for (int i = tid; i < N_TOK; i += 1024) {
            unsigned v = u[i];
            if ((v & hm) == pref) atomicAdd(&hist[(v >> shift) & 255], 1);
        }
        __syncthreads();
        if (tid == 0) {
            int K = s_K, cum = 0, sel = 0;
            for (int b = 255; b >= 0; b--) {
                int c = hist[b];
                if (cum + c >= K) { sel = b; s_K = K - cum; break; }
                cum += c;
            }
            s_prefix = pref | ((unsigned)sel << shift);
        }
        __syncthreads();
    }
    unsigned thr = s_prefix;

    // count strictly greater
    {
        int c = 0;
        for (int i = tid; i < N_TOK; i += 1024) if (u[i] > thr) c++;
#pragma unroll
        for (int o = 16; o > 0; o >>= 1) c += __shfl_down_sync(0xffffffffu, c, o);
        if ((tid & 31) == 0) atomicAdd(&s_cgt, c);
    }
    __syncthreads();
    int cgt = s_cgt;
    int ties_needed = CAP - cgt;

    // ordered compaction (index order, matching lax.top_k tie-break)
    int warp = tid >> 5, lane = tid & 31;
    unsigned lmask = (1u << lane) - 1u;
    for (int ch = 0; ch < 16; ch++) {
        int i = ch * 1024 + tid;
        unsigned v = u[i];
        int fgt = (v > thr);
        int fti = (v == thr);
        unsigned bg = __ballot_sync(0xffffffffu, fgt);
        unsigned bt = __ballot_sync(0xffffffffu, fti);
        if (lane == 0) { wtot_gt[warp] = __popc(bg); wtot_ti[warp] = __popc(bt); }
        __syncthreads();
        if (tid == 0) {
            int ag = base_gt, at = base_ti;
            for (int w = 0; w < 32; w++) {
                int tg = wtot_gt[w], tt = wtot_ti[w];
                wtot_gt[w] = ag; wtot_ti[w] = at;
                ag += tg; at += tt;
            }
            base_gt = ag; base_ti = at;
        }
        __syncthreads();
        int pg = wtot_gt[warp] + __popc(bg & lmask);
        int pt = wtot_ti[warp] + __popc(bt & lmask);
        if (fgt) {
            g_idx[e * CAP + pg] = i;
            g_vals[e * CAP + pg] = sc[i];
        }
        if (fti && pt < ties_needed) {
            int s2 = cgt + pt;
            g_idx[e * CAP + s2] = i;
            g_vals[e * CAP + s2] = sc[i];
        }
        __syncthreads();
    }
}

// ---------------- zero pred + counts -----------------------------------------
__global__ void k_zero() {
    int i = blockIdx.x * blockDim.x + threadIdx.x;
    if (i < NELEM) g_pred[i] = 0.f;
    if (i < N_TOK) g_counts[i] = 0.f;
}

// ---------------- counts scatter ----------------------------------------------
__global__ void k_counts() {
    int i = blockIdx.x * blockDim.x + threadIdx.x;
    if (i < E_ * CAP) atomicAdd(&g_counts[g_idx[i]], 1.0f);
}

// ---------------- expert GEMM (gathered A) + weighted scatter into pred ------
// grid: (ntile=8, mtile=32, expert=8), 256 threads, 64x64x32 tile, 4x4 micro
__global__ void k_gemm(const float* __restrict__ expert_w) {
    __shared__ __align__(16) float As[32][68];
    __shared__ __align__(16) float Bs[32][68];
    __shared__ int   s_rows[64];
    __shared__ float s_vals[64];

    int bn = blockIdx.x, bm = blockIdx.y, e = blockIdx.z;
    int tid = threadIdx.x;
    int tx = tid & 15, ty = tid >> 4;

    if (tid < 64) {
        s_rows[tid] = g_idx[e * CAP + bm * 64 + tid];
        s_vals[tid] = g_vals[e * CAP + bm * 64 + tid];
    }

    const float* W = expert_w + (size_t)e * TWO_D * TWO_D + bn * 64;

    float acc[4][4];
#pragma unroll
    for (int i = 0; i < 4; i++)
#pragma unroll
        for (int j = 0; j < 4; j++) acc[i][j] = 0.f;

    for (int k0 = 0; k0 < TWO_D; k0 += 32) {
        __syncthreads();
#pragma unroll
        for (int i = 0; i < 8; i++) {
            int l = tid + i * 256;
            int m = l >> 5, k = l & 31;
            As[k][m] = g_x_eff[(size_t)s_rows[m] * TWO_D + k0 + k];
        }
#pragma unroll
        for (int i = 0; i < 8; i++) {
            int l = tid + i * 256;
            int kr = l >> 6, n = l & 63;
            Bs[kr][n] = W[(size_t)(k0 + kr) * TWO_D + n];
        }
        __syncthreads();
#pragma unroll
        for (int kk = 0; kk < 32; kk++) {
            float4 a = *(const float4*)&As[kk][ty * 4];
            float4 b = *(const float4*)&Bs[kk][tx * 4];
            acc[0][0] += a.x * b.x; acc[0][1] += a.x * b.y; acc[0][2] += a.x * b.z; acc[0][3] += a.x * b.w;
            acc[1][0] += a.y * b.x; acc[1][1] += a.y * b.y; acc[1][2] += a.y * b.z; acc[1][3] += a.y * b.w;
            acc[2][0] += a.z * b.x; acc[2][1] += a.z * b.y; acc[2][2] += a.z * b.z; acc[2][3] += a.z * b.w;
            acc[3][0] += a.w * b.x; acc[3][1] += a.w * b.y; acc[3][2] += a.w * b.z; acc[3][3] += a.w * b.w;
        }
    }

#pragma unroll
    for (int i = 0; i < 4; i++) {
        int token = s_rows[ty * 4 + i];
        float vv = s_vals[ty * 4 + i];
        float* p = g_pred + (size_t)token * TWO_D + bn * 64 + tx * 4;
#pragma unroll
        for (int j = 0; j < 4; j++)
            atomicAdd(&p[j], vv * acc[i][j]);
    }
}

// ---------------- state update ------------------------------------------------
__global__ void k_update(float lr) {
    int i = blockIdx.x * blockDim.x + threadIdx.x;
    if (i >= NELEM) return;
    float r = g_x_target[i] - g_pred[i];
    r = fminf(fmaxf(r, -10.f), 10.f);
    g_x_states[i] += lr * r;
}

// ---------------- normalize + tanh activate -----------------------------------
__global__ void k_activate(const float* __restrict__ act_bias) {
    int i = blockIdx.x * blockDim.x + threadIdx.x;
    if (i >= NPAIR) return;
    int n = i >> 8;
    int d = i & 255;
    float dn = fmaxf(g_counts[n], 1.0f);
    float2 p = ((float2*)g_pred)[i];
    float2 r;
    r.x = tanhf(p.x / dn + act_bias[2 * d + 0]);
    r.y = tanhf(p.y / dn + act_bias[2 * d + 1]);
    ((float2*)g_x_states)[i] = r;
}

// ---------------- final output + residual norm --------------------------------
__global__ void k_output(float* __restrict__ out) {
    __shared__ double sd[256];
    int tid = threadIdx.x;
    int i = blockIdx.x * blockDim.x + tid;
    double sloc = 0.0;
    if (i < NPAIR) {
        float2 xs = ((float2*)g_x_states)[i];
        float2 tg = ((float2*)g_x_target)[i];
        float2 pg = ((float2*)g_pred)[i];
        float2 o;
        o.x = xs.x + 0.5f * (tg.x - pg.x);
        o.y = xs.y + 0.5f * (tg.y - pg.y);
        ((float2*)out)[i] = o;
        float dr = tg.x - pg.x, di = tg.y - pg.y;
        sloc = (double)sqrtf(dr * dr + di * di);
    }
    sd[tid] = sloc;
    __syncthreads();
    for (int s = 128; s > 0; s >>= 1) {
        if (tid < s) sd[tid] += sd[tid + s];
        __syncthreads();
    }
    if (tid == 0) atomicAdd(&g_resnorm, sd[0]);
}

__global__ void k_final(float* __restrict__ out, int pos) {
    out[pos] = (float)(g_resnorm / (double)NPAIR);
}

// ---------------- host launcher -----------------------------------------------
extern "C" void kernel_launch(void* const* d_in, const int* in_sizes, int n_in,
                              void* d_out, int out_size) {
    const float* x        = (const float*)d_in[0];
    const float* dgains   = (const float*)d_in[1];
    const float* cosp     = (const float*)d_in[2];
    const float* sinp     = (const float*)d_in[3];
    const float* gate_w   = (const float*)d_in[4];
    const float* expert_w = (const float*)d_in[5];
    const float* act_bias = (const float*)d_in[6];
    float* out = (float*)d_out;

    cudaFuncSetAttribute(k_topk, cudaFuncAttributeMaxDynamicSharedMemorySize, 64 * 1024);

    const int EB = 256;
    dim3 gemm_grid(TWO_D / 64, CAP / 64, E_);   // (8, 32, 8)

    k_init<<<(NPAIR + EB - 1) / EB, EB>>>(x, cosp, sinp);

    float lr = 0.5f;
    for (int it = 0; it < 8; it++) {
        k_delays_gate<<<N_TOK, 256>>>(dgains, gate_w);
        k_topk<<<E_, 1024, 64 * 1024>>>();
        k_zero<<<(NELEM + EB - 1) / EB, EB>>>();
        if (it == 7)
            k_counts<<<(E_ * CAP + EB - 1) / EB, EB>>>();
        k_gemm<<<gemm_grid, 256>>>(expert_w);
        if (it < 7) {
            k_update<<<(NELEM + EB - 1) / EB, EB>>>(lr);
            lr *= 0.85f;
        }
    }

    k_activate<<<(NPAIR + EB - 1) / EB, EB>>>(act_bias);

    // gradient pass
    k_delays_gate<<<N_TOK, 256>>>(dgains, gate_w);
    k_topk<<<E_, 1024, 64 * 1024>>>();
    k_zero<<<(NELEM + EB - 1) / EB, EB>>>();
    k_gemm<<<gemm_grid, 256>>>(expert_w);

    k_output<<<(NPAIR + EB - 1) / EB, EB>>>(out);
    k_final<<<1, 1>>>(out, out_size - 1);
}

// round 2
// speedup vs baseline: 1.3828x; 1.3828x over previous
#include <cuda_runtime.h>
#include <math.h>

#define B_      2
#define T_      8192
#define D_      256
#define E_      8
#define TWO_D   512
#define N_TOK   16384
#define CAP     2048
#define NELEM   (N_TOK * TWO_D)   /* 8388608 */
#define NPAIR   (N_TOK * D_)      /* 4194304 */

// ---------------- scratch (device globals; no allocation allowed) ------------
__device__ float  g_x_states[NELEM];
__device__ float  g_x_target[NELEM];
__device__ float  g_x_eff[NELEM];
__device__ float  g_pred[NELEM];
__device__ float  g_scoresT[E_ * N_TOK];
__device__ int    g_idx[E_ * CAP];
__device__ float  g_vals[E_ * CAP];
__device__ float  g_counts[N_TOK];
__device__ double g_resnorm;

// ---------------- init: copy x -> x_states, compute phase targets ------------
__global__ void k_init(const float* __restrict__ x,
                       const float* __restrict__ cosp,
                       const float* __restrict__ sinp) {
    int i = blockIdx.x * blockDim.x + threadIdx.x;
    if (i == 0) g_resnorm = 0.0;
    if (i >= NPAIR) return;
    int n = i >> 8;          // token index
    int d = i & 255;
    int t = n & (T_ - 1);
    const float2* x2 = (const float2*)x;
    float2 cur = x2[i];
    ((float2*)g_x_states)[i] = cur;
    float2 tg;
    if (t == 0) {
        tg = cur;
    } else {
        float2 p = x2[i - 256];          // (n-1, d)
        float c = cosp[d], s = sinp[d];
        tg.x = p.x * c - p.y * s;
        tg.y = p.x * s + p.y * c;
    }
    ((float2*)g_x_target)[i] = tg;
}

// ------------- fused: apply prime delays + gate logits + softmax -------------
// one block per token, 256 threads (one per d)
__global__ void k_delays_gate(const float* __restrict__ dgains,
                              const float* __restrict__ gate_w) {
    __shared__ float s_gw[TWO_D * E_];   // 4096 floats
    __shared__ float s_red[64];          // 8 warps x 8 experts
    int n = blockIdx.x;
    int d = threadIdx.x;

    for (int i = d; i < TWO_D * E_; i += 256) s_gw[i] = gate_w[i];

    int t = n & (T_ - 1);
    const float2* xs2 = (const float2*)g_x_states;
    float2 v = xs2[n * 256 + d];

    const int taus[4] = {1, 2, 3, 5};
#pragma unroll
    for (int q = 0; q < 4; q++) {
        int tau = taus[q];
        if (t >= tau) {
            float2 s = xs2[(n - tau) * 256 + d];
            float gr = dgains[(q * 256 + d) * 2 + 0];
            float gi = dgains[(q * 256 + d) * 2 + 1];
            v.x += s.x * gr - s.y * gi;
            v.y += s.x * gi + s.y * gr;
        }
    }
    ((float2*)g_x_eff)[n * 256 + d] = v;
    __syncthreads();

    float p[E_];
#pragma unroll
    for (int e = 0; e < E_; e++)
        p[e] = v.x * s_gw[(2 * d) * E_ + e] + v.y * s_gw[(2 * d + 1) * E_ + e];

#pragma unroll
    for (int o = 16; o > 0; o >>= 1)
#pragma unroll
        for (int e = 0; e < E_; e++)
            p[e] += __shfl_down_sync(0xffffffffu, p[e], o);

    int warp = d >> 5, lane = d & 31;
    if (lane == 0)
#pragma unroll
        for (int e = 0; e < E_; e++) s_red[warp * E_ + e] = p[e];
    __syncthreads();

    if (d < E_) {
        float logit = 0.f;
#pragma unroll
        for (int w = 0; w < 8; w++) logit += s_red[w * E_ + d];
        float m = logit;
#pragma unroll
        for (int o = 4; o > 0; o >>= 1)
            m = fmaxf(m, __shfl_xor_sync(0x000000ffu, m, o, 8));
        float ex = expf(logit - m);
        float s = ex;
#pragma unroll
        for (int o = 4; o > 0; o >>= 1)
            s += __shfl_xor_sync(0x000000ffu, s, o, 8);
        g_scoresT[d * N_TOK + n] = ex / s;
    }
}

// -------- per-expert top-CAP selection (byte radix select + ordered compact) -
// 8 blocks (one per expert), 1024 threads, 64KB dynamic smem
__global__ void k_topk() {
    extern __shared__ unsigned u[];      // 16384 flipped keys
    __shared__ int      hist[256];
    __shared__ unsigned s_prefix;
    __shared__ int      s_K;
    __shared__ int      s_cgt;
    __shared__ int      base_gt, base_ti;
    __shared__ int      wtot_gt[32], wtot_ti[32];

    int e = blockIdx.x;
    int tid = threadIdx.x;
    const float* sc = g_scoresT + e * N_TOK;

    for (int i = tid; i < N_TOK; i += 1024) {
        unsigned v = __float_as_uint(sc[i]);
        v = (v & 0x80000000u) ? ~v : (v | 0x80000000u);
        u[i] = v;
    }
    if (tid == 0) { s_prefix = 0u; s_K = CAP; s_cgt = 0; base_gt = 0; base_ti = 0; }
    __syncthreads();

    // radix select: find value of CAP-th largest key
    for (int level = 0; level < 4; level++) {
        int shift = 24 - 8 * level;
        unsigned hm = (level == 0) ? 0u : (0xFFFFFFFFu << (shift + 8));
        if (tid < 256) hist[tid] = 0;
        __syncthreads();
        unsigned pref = s_prefix;
        for (int i = tid; i < N_TOK; i += 1024) {
            unsigned v = u[i];
            if ((v & hm) == pref) atomicAdd(&hist[(v >> shift) & 255], 1);
        }
        __syncthreads();
        if (tid == 0) {
            int K = s_K, cum = 0, sel = 0;
            for (int b = 255; b >= 0; b--) {
                int c = hist[b];
                if (cum + c >= K) { sel = b; s_K = K - cum; break; }
                cum += c;
            }
            s_prefix = pref | ((unsigned)sel << shift);
        }
        __syncthreads();
    }
    unsigned thr = s_prefix;

    // count strictly greater
    {
        int c = 0;
        for (int i = tid; i < N_TOK; i += 1024) if (u[i] > thr) c++;
#pragma unroll
        for (int o = 16; o > 0; o >>= 1) c += __shfl_down_sync(0xffffffffu, c, o);
        if ((tid & 31) == 0) atomicAdd(&s_cgt, c);
    }
    __syncthreads();
    int cgt = s_cgt;
    int ties_needed = CAP - cgt;

    // ordered compaction (index order, matching lax.top_k tie-break)
    int warp = tid >> 5, lane = tid & 31;
    unsigned lmask = (1u << lane) - 1u;
    for (int ch = 0; ch < 16; ch++) {
        int i = ch * 1024 + tid;
        unsigned v = u[i];
        int fgt = (v > thr);
        int fti = (v == thr);
        unsigned bg = __ballot_sync(0xffffffffu, fgt);
        unsigned bt = __ballot_sync(0xffffffffu, fti);
        if (lane == 0) { wtot_gt[warp] = __popc(bg); wtot_ti[warp] = __popc(bt); }
        __syncthreads();
        if (tid == 0) {
            int ag = base_gt, at = base_ti;
            for (int w = 0; w < 32; w++) {
                int tg = wtot_gt[w], tt = wtot_ti[w];
                wtot_gt[w] = ag; wtot_ti[w] = at;
                ag += tg; at += tt;
            }
            base_gt = ag; base_ti = at;
        }
        __syncthreads();
        int pg = wtot_gt[warp] + __popc(bg & lmask);
        int pt = wtot_ti[warp] + __popc(bt & lmask);
        if (fgt) {
            g_idx[e * CAP + pg] = i;
            g_vals[e * CAP + pg] = sc[i];
        }
        if (fti && pt < ties_needed) {
            int s2 = cgt + pt;
            g_idx[e * CAP + s2] = i;
            g_vals[e * CAP + s2] = sc[i];
        }
        __syncthreads();
    }
}

// ---------------- zero pred + counts -----------------------------------------
__global__ void k_zero() {
    int i = blockIdx.x * blockDim.x + threadIdx.x;
    if (i < NELEM) g_pred[i] = 0.f;
    if (i < N_TOK) g_counts[i] = 0.f;
}

// ---------------- counts scatter ----------------------------------------------
__global__ void k_counts() {
    int i = blockIdx.x * blockDim.x + threadIdx.x;
    if (i < E_ * CAP) atomicAdd(&g_counts[g_idx[i]], 1.0f);
}

// ---------------- expert GEMM (gathered A) + weighted scatter into pred ------
// grid: (ntile=4, mtile=16, expert=8), 256 threads, 128x128x16 tile, 8x8 micro,
// register double-buffering of the next K-stage.
__global__ void __launch_bounds__(256, 2) k_gemm(const float* __restrict__ expert_w) {
    __shared__ __align__(16) float As[16][132];
    __shared__ __align__(16) float Bs[16][132];
    __shared__ int   s_rows[128];
    __shared__ float s_vals[128];

    int bn = blockIdx.x, bm = blockIdx.y, e = blockIdx.z;
    int tid = threadIdx.x;
    int tx = tid & 15, ty = tid >> 4;

    if (tid < 128) {
        s_rows[tid] = g_idx[e * CAP + bm * 128 + tid];
        s_vals[tid] = g_vals[e * CAP + bm * 128 + tid];
    }
    __syncthreads();

    const float* W = expert_w + (size_t)e * TWO_D * TWO_D + bn * 128;

    // A-load mapping: thread covers row (tid&127), k-quad pair at 8*(tid>>7)
    int am = tid & 127;
    int ah = (tid >> 7) * 8;                    // 0 or 8
    size_t arow = (size_t)s_rows[am] * TWO_D;

    // B-load mapping: thread covers float4 column (tid&31), rows (tid>>5), +8
    int bc = (tid & 31) * 4;
    int bk = tid >> 5;

    float4 pa0, pa1, pb0, pb1;

    // prefetch stage 0
    pa0 = *(const float4*)&g_x_eff[arow + ah];
    pa1 = *(const float4*)&g_x_eff[arow + ah + 4];
    pb0 = *(const float4*)&W[(size_t)bk * TWO_D + bc];
    pb1 = *(const float4*)&W[(size_t)(bk + 8) * TWO_D + bc];

    float acc[8][8];
#pragma unroll
    for (int i = 0; i < 8; i++)
#pragma unroll
        for (int j = 0; j < 8; j++) acc[i][j] = 0.f;

    for (int k0 = 0; k0 < TWO_D; k0 += 16) {
        __syncthreads();
        As[ah + 0][am] = pa0.x; As[ah + 1][am] = pa0.y;
        As[ah + 2][am] = pa0.z; As[ah + 3][am] = pa0.w;
        As[ah + 4][am] = pa1.x; As[ah + 5][am] = pa1.y;
        As[ah + 6][am] = pa1.z; As[ah + 7][am] = pa1.w;
        *(float4*)&Bs[bk][bc]     = pb0;
        *(float4*)&Bs[bk + 8][bc] = pb1;
        __syncthreads();

        if (k0 + 16 < TWO_D) {
            int kn = k0 + 16;
            pa0 = *(const float4*)&g_x_eff[arow + kn + ah];
            pa1 = *(const float4*)&g_x_eff[arow + kn + ah + 4];
            pb0 = *(const float4*)&W[(size_t)(kn + bk) * TWO_D + bc];
            pb1 = *(const float4*)&W[(size_t)(kn + bk + 8) * TWO_D + bc];
        }

#pragma unroll
        for (int kk = 0; kk < 16; kk++) {
            float4 a0 = *(const float4*)&As[kk][ty * 4];
            float4 a1 = *(const float4*)&As[kk][ty * 4 + 64];
            float4 b0 = *(const float4*)&Bs[kk][tx * 4];
            float4 b1 = *(const float4*)&Bs[kk][tx * 4 + 64];
            float av[8] = {a0.x, a0.y, a0.z, a0.w, a1.x, a1.y, a1.z, a1.w};
            float bv[8] = {b0.x, b0.y, b0.z, b0.w, b1.x, b1.y, b1.z, b1.w};
#pragma unroll
            for (int i = 0; i < 8; i++)
#pragma unroll
                for (int j = 0; j < 8; j++)
                    acc[i][j] += av[i] * bv[j];
        }
    }

#pragma unroll
    for (int i = 0; i < 8; i++) {
        int m = ty * 4 + (i & 3) + (i >> 2) * 64;
        int token = s_rows[m];
        float vv = s_vals[m];
        float* p = g_pred + (size_t)token * TWO_D + bn * 128;
#pragma unroll
        for (int j = 0; j < 8; j++) {
            int n = tx * 4 + (j & 3) + (j >> 2) * 64;
            atomicAdd(&p[n], vv * acc[i][j]);
        }
    }
}

// ---------------- state update ------------------------------------------------
__global__ void k_update(float lr) {
    int i = blockIdx.x * blockDim.x + threadIdx.x;
    if (i >= NELEM) return;
    float r = g_x_target[i] - g_pred[i];
    r = fminf(fmaxf(r, -10.f), 10.f);
    g_x_states[i] += lr * r;
}

// ---------------- normalize + tanh activate -----------------------------------
__global__ void k_activate(const float* __restrict__ act_bias) {
    int i = blockIdx.x * blockDim.x + threadIdx.x;
    if (i >= NPAIR) return;
    int n = i >> 8;
    int d = i & 255;
    float dn = fmaxf(g_counts[n], 1.0f);
    float2 p = ((float2*)g_pred)[i];
    float2 r;
    r.x = tanhf(p.x / dn + act_bias[2 * d + 0]);
    r.y = tanhf(p.y / dn + act_bias[2 * d + 1]);
    ((float2*)g_x_states)[i] = r;
}

// ---------------- final output + residual norm --------------------------------
__global__ void k_output(float* __restrict__ out) {
    __shared__ double sd[256];
    int tid = threadIdx.x;
    int i = blockIdx.x * blockDim.x + tid;
    double sloc = 0.0;
    if (i < NPAIR) {
        float2 xs = ((float2*)g_x_states)[i];
        float2 tg = ((float2*)g_x_target)[i];
        float2 pg = ((float2*)g_pred)[i];
        float2 o;
        o.x = xs.x + 0.5f * (tg.x - pg.x);
        o.y = xs.y + 0.5f * (tg.y - pg.y);
        ((float2*)out)[i] = o;
        float dr = tg.x - pg.x, di = tg.y - pg.y;
        sloc = (double)sqrtf(dr * dr + di * di);
    }
    sd[tid] = sloc;
    __syncthreads();
    for (int s = 128; s > 0; s >>= 1) {
        if (tid < s) sd[tid] += sd[tid + s];
        __syncthreads();
    }
    if (tid == 0) atomicAdd(&g_resnorm, sd[0]);
}

__global__ void k_final(float* __restrict__ out, int pos) {
    out[pos] = (float)(g_resnorm / (double)NPAIR);
}

// ---------------- host launcher -----------------------------------------------
extern "C" void kernel_launch(void* const* d_in, const int* in_sizes, int n_in,
                              void* d_out, int out_size) {
    const float* x        = (const float*)d_in[0];
    const float* dgains   = (const float*)d_in[1];
    const float* cosp     = (const float*)d_in[2];
    const float* sinp     = (const float*)d_in[3];
    const float* gate_w   = (const float*)d_in[4];
    const float* expert_w = (const float*)d_in[5];
    const float* act_bias = (const float*)d_in[6];
    float* out = (float*)d_out;

    cudaFuncSetAttribute(k_topk, cudaFuncAttributeMaxDynamicSharedMemorySize, 64 * 1024);

    const int EB = 256;
    dim3 gemm_grid(TWO_D / 128, CAP / 128, E_);   // (4, 16, 8)

    k_init<<<(NPAIR + EB - 1) / EB, EB>>>(x, cosp, sinp);

    float lr = 0.5f;
    for (int it = 0; it < 8; it++) {
        k_delays_gate<<<N_TOK, 256>>>(dgains, gate_w);
        k_topk<<<E_, 1024, 64 * 1024>>>();
        k_zero<<<(NELEM + EB - 1) / EB, EB>>>();
        if (it == 7)
            k_counts<<<(E_ * CAP + EB - 1) / EB, EB>>>();
        k_gemm<<<gemm_grid, 256>>>(expert_w);
        if (it < 7) {
            k_update<<<(NELEM + EB - 1) / EB, EB>>>(lr);
            lr *= 0.85f;
        }
    }

    k_activate<<<(NPAIR + EB - 1) / EB, EB>>>(act_bias);

    // gradient pass
    k_delays_gate<<<N_TOK, 256>>>(dgains, gate_w);
    k_topk<<<E_, 1024, 64 * 1024>>>();
    k_zero<<<(NELEM + EB - 1) / EB, EB>>>();
    k_gemm<<<gemm_grid, 256>>>(expert_w);

    k_output<<<(NPAIR + EB - 1) / EB, EB>>>(out);
    k_final<<<1, 1>>>(out, out_size - 1);
}